// round 16
// baseline (speedup 1.0000x reference)
#include <cuda_runtime.h>
#include <cooperative_groups.h>
#include <cstdint>

namespace cg = cooperative_groups;

// WaveRNN_77927886618842 — 2D acoustic FDTD, 500 steps, 8 shots, 256x256, 128 rec.
// R16 (= R8..R15 resubmit; all prior rounds were GPU-broker acquisition timeouts):
// 16-CTA clusters (128 SMs busy, halves per-SMSP issue work vs R4's 64 CTAs),
// HW cluster.sync per step (R4-proven; beats mbarrier handshakes per R5/R7),
// halo rows PUSHED register->neighbor apron SMEM so post-sync reads are local.

#define NT   500
#define NS   8
#define NZ   256
#define NX   256
#define NREC 128
#define CPS  16             // CTAs per shot == cluster size (nonportable)
#define ROWS 16             // NZ / CPS rows per CTA
#define TPB  512
#define DT_OVER_DX 1.0e-4f  // 0.001 / 10.0

#define AP_U (ROWS * 64)        // apron: up-neighbor's bottom row (my rm1 @ row 0)
#define AP_D ((ROWS + 1) * 64)  // apron: down-neighbor's top row (my r2 @ row ROWS-1)

__global__ void __launch_bounds__(TPB, 1)
wave_cluster_kernel(const float* __restrict__ x,    // (NT, NS)
                    const float* __restrict__ vp,   // (NZ, NX)
                    const int*   __restrict__ src,  // (NS, 2)
                    const int*   __restrict__ rec,  // (NS, NREC, 2)
                    float*       __restrict__ out)  // (NT, NS, NREC)
{
    extern __shared__ float smem[];
    float* bufA = smem;                       // (ROWS+2)*NX floats = 18 KB
    float* bufB = smem + (ROWS + 2) * NX;     // 18 KB

    cg::cluster_group cluster = cg::this_cluster();
    const int rank = cluster.block_rank();        // 0..15 (z-slab index)
    const int shot = blockIdx.x / CPS;            // 0..7
    const int tid  = threadIdx.x;
    const int lane = tid & 31;
    const int x4   = tid & 63;                    // float4 column 0..63
    const int xs4  = x4 * 4;                      // scalar column of .x
    const int zg   = tid >> 6;                    // 0..7, two rows each (warp-uniform)
    const int zl0  = zg * 2;                      // local rows zl0, zl0+1
    const int gz0  = rank * ROWS + zl0;           // global z of row 0

    float4* Av = (float4*)bufA;
    float4* Bv = (float4*)bufB;
    const float4 zero4 = make_float4(0.f, 0.f, 0.f, 0.f);

    // ---- init: zero own rows + aprons of both buffers ----
    Av[zl0 * 64 + x4]       = zero4;
    Av[(zl0 + 1) * 64 + x4] = zero4;
    Bv[zl0 * 64 + x4]       = zero4;
    Bv[(zl0 + 1) * 64 + x4] = zero4;
    if (zg == 0) { Av[AP_U + x4] = zero4; Av[AP_D + x4] = zero4; }
    if (zg == 1) { Bv[AP_U + x4] = zero4; Bv[AP_D + x4] = zero4; }

    // ---- c2 = (vp * DT/DX)^2 into registers ----
    float4 c2a, c2b;
    {
        const float4* vpv = (const float4*)vp;
        float4 v0 = vpv[gz0 * 64 + x4];
        float4 v1 = vpv[(gz0 + 1) * 64 + x4];
        c2a.x = v0.x * DT_OVER_DX; c2a.y = v0.y * DT_OVER_DX;
        c2a.z = v0.z * DT_OVER_DX; c2a.w = v0.w * DT_OVER_DX;
        c2b.x = v1.x * DT_OVER_DX; c2b.y = v1.y * DT_OVER_DX;
        c2b.z = v1.z * DT_OVER_DX; c2b.w = v1.w * DT_OVER_DX;
        c2a.x *= c2a.x; c2a.y *= c2a.y; c2a.z *= c2a.z; c2a.w *= c2a.w;
        c2b.x *= c2b.x; c2b.y *= c2b.y; c2b.z *= c2b.z; c2b.w *= c2b.w;
    }

    // ---- source cell ownership ----
    const int sz  = src[2 * shot];
    const int sx  = src[2 * shot + 1];
    const int sx4 = sx >> 2;
    const int sxl = sx & 3;
    const bool src0 = (sz == gz0)     && (sx4 == x4);
    const bool src1 = (sz == gz0 + 1) && (sx4 == x4);
    const float* __restrict__ xs = x + shot;      // x[t*NS + shot] = xs[t*NS]

    // ---- receiver assignment: thread tid<128 owns receiver tid of this shot ----
    int  rzl = 0, rxp = 0;
    bool mine = false;
    if (tid < NREC) {
        int rz = rec[(shot * NREC + tid) * 2];
        rxp    = rec[(shot * NREC + tid) * 2 + 1];
        mine   = ((rz >> 4) == rank);             // ROWS == 16
        rzl    = rz & 15;
    }
    float* __restrict__ outp = out + shot * NREC + tid;   // += NS*NREC per step

    // ---- remote apron pointers for halo PUSH (fixed for the whole run) ----
    float4* upA_r = (rank > 0)       ? (float4*)cluster.map_shared_rank((void*)bufA, rank - 1) : nullptr;
    float4* upB_r = (rank > 0)       ? (float4*)cluster.map_shared_rank((void*)bufB, rank - 1) : nullptr;
    float4* dnA_r = (rank < CPS - 1) ? (float4*)cluster.map_shared_rank((void*)bufA, rank + 1) : nullptr;
    float4* dnB_r = (rank < CPS - 1) ? (float4*)cluster.map_shared_rank((void*)bufB, rank + 1) : nullptr;

    float4 pva = zero4, pvb = zero4;   // p_prev for the two owned rows

    cluster.sync();   // zeros + aprons visible cluster-wide before step 0

    #pragma unroll 1
    for (int t = 0; t < NT; ++t) {
        const bool odd = (t & 1) != 0;
        float4* curv = odd ? Bv : Av;
        float4* nxtv = odd ? Av : Bv;
        // push targets: aprons of the buffer that becomes cur at step t+1
        float4* upNxt = odd ? upA_r : upB_r;
        float4* dnNxt = odd ? dnA_r : dnB_r;
        float*  curs  = (float*)curv;

        // ---- loads: sync-gated apron rows FIRST (freshest writes), then own
        float4 rm1 = (zg > 0) ? curv[(zl0 - 1) * 64 + x4] : curv[AP_U + x4];
        float4 r2  = (zg < 7) ? curv[(zl0 + 2) * 64 + x4] : curv[AP_D + x4];
        float4 r0  = curv[zl0 * 64 + x4];
        float4 r1  = curv[(zl0 + 1) * 64 + x4];

        float L0 = __shfl_up_sync(0xffffffffu, r0.w, 1);
        float R0 = __shfl_down_sync(0xffffffffu, r0.x, 1);
        float L1 = __shfl_up_sync(0xffffffffu, r1.w, 1);
        float R1 = __shfl_down_sync(0xffffffffu, r1.x, 1);
        if (lane == 0) {
            L0 = (x4 == 0) ? 0.f : curs[zl0 * NX + xs4 - 1];
            L1 = (x4 == 0) ? 0.f : curs[(zl0 + 1) * NX + xs4 - 1];
        }
        if (lane == 31) {
            R0 = (x4 == 63) ? 0.f : curs[zl0 * NX + xs4 + 4];
            R1 = (x4 == 63) ? 0.f : curs[(zl0 + 1) * NX + xs4 + 4];
        }

        // row zl0: up=rm1, dn=r1
        float4 lap0;
        lap0.x = rm1.x + r1.x + L0   + r0.y - 4.f * r0.x;
        lap0.y = rm1.y + r1.y + r0.x + r0.z - 4.f * r0.y;
        lap0.z = rm1.z + r1.z + r0.y + r0.w - 4.f * r0.z;
        lap0.w = rm1.w + r1.w + r0.z + R0   - 4.f * r0.w;
        float4 p0;
        p0.x = 2.f * r0.x - pva.x + c2a.x * lap0.x;
        p0.y = 2.f * r0.y - pva.y + c2a.y * lap0.y;
        p0.z = 2.f * r0.z - pva.z + c2a.z * lap0.z;
        p0.w = 2.f * r0.w - pva.w + c2a.w * lap0.w;
        pva = r0;

        // row zl0+1: up=r0, dn=r2
        float4 lap1;
        lap1.x = r0.x + r2.x + L1   + r1.y - 4.f * r1.x;
        lap1.y = r0.y + r2.y + r1.x + r1.z - 4.f * r1.y;
        lap1.z = r0.z + r2.z + r1.y + r1.w - 4.f * r1.z;
        lap1.w = r0.w + r2.w + r1.z + R1   - 4.f * r1.w;
        float4 p1;
        p1.x = 2.f * r1.x - pvb.x + c2b.x * lap1.x;
        p1.y = 2.f * r1.y - pvb.y + c2b.y * lap1.y;
        p1.z = 2.f * r1.z - pvb.z + c2b.z * lap1.z;
        p1.w = 2.f * r1.w - pvb.w + c2b.w * lap1.w;
        pvb = r1;

        // source injection
        if (src0 | src1) {
            int t_off = (t + 2 < NT - 1) ? (t + 2) : (NT - 1);
            float amp = xs[t_off * NS] + xs[t * NS];
            if (src0) {
                if      (sxl == 0) p0.x += amp;
                else if (sxl == 1) p0.y += amp;
                else if (sxl == 2) p0.z += amp;
                else               p0.w += amp;
            } else {
                if      (sxl == 0) p1.x += amp;
                else if (sxl == 1) p1.y += amp;
                else if (sxl == 2) p1.z += amp;
                else               p1.w += amp;
            }
        }

        // ---- halo PUSH: edge rows straight from registers into neighbor aprons
        // (DSMEM write latency overlaps the tail of this step; cluster.sync
        //  release/acquire orders it; buffer ping-pong + per-slot single
        //  writer prevent races; boundary aprons stay zero = pad boundary)
        if (zg == 0 && upNxt) upNxt[AP_D + x4] = p0;  // my row 0      -> up nbr r2
        if (zg == 7 && dnNxt) dnNxt[AP_U + x4] = p1;  // my row ROWS-1 -> dn nbr rm1

        nxtv[zl0 * 64 + x4]       = p0;
        nxtv[(zl0 + 1) * 64 + x4] = p1;

        cluster.sync();   // step t complete cluster-wide (incl. apron pushes)

        // receiver gather for step t (all-local SMEM reads)
        if (mine) {
            const float* ns = (const float*)nxtv;
            outp[t * (NS * NREC)] = ns[rzl * NX + rxp];
        }
    }
}

extern "C" void kernel_launch(void* const* d_in, const int* in_sizes, int n_in,
                              void* d_out, int out_size)
{
    const float* x   = (const float*)d_in[0];
    const float* vp  = (const float*)d_in[1];
    const int*   src = (const int*)d_in[2];
    const int*   rec = (const int*)d_in[3];
    float*       out = (float*)d_out;
    (void)in_sizes; (void)n_in; (void)out_size;

    const size_t smem_bytes = 2u * (ROWS + 2) * NX * sizeof(float);

    cudaFuncSetAttribute(wave_cluster_kernel,
                         cudaFuncAttributeMaxDynamicSharedMemorySize, (int)smem_bytes);
    cudaFuncSetAttribute(wave_cluster_kernel,
                         cudaFuncAttributeNonPortableClusterSizeAllowed, 1);

    cudaLaunchConfig_t cfg = {};
    cfg.gridDim  = dim3(NS * CPS, 1, 1);
    cfg.blockDim = dim3(TPB, 1, 1);
    cfg.dynamicSmemBytes = smem_bytes;
    cudaLaunchAttribute attrs[1];
    attrs[0].id = cudaLaunchAttributeClusterDimension;
    attrs[0].val.clusterDim.x = CPS;
    attrs[0].val.clusterDim.y = 1;
    attrs[0].val.clusterDim.z = 1;
    cfg.attrs = attrs;
    cfg.numAttrs = 1;

    cudaLaunchKernelEx(&cfg, wave_cluster_kernel, x, vp, src, rec, out);
}

// round 17
// speedup vs baseline: 1.5302x; 1.5302x over previous
#include <cuda_runtime.h>
#include <cooperative_groups.h>
#include <cstdint>

namespace cg = cooperative_groups;

// WaveRNN_77927886618842 — 2D acoustic FDTD, 500 steps, 8 shots, 256x256, 128 rec.
// R17: back to the MEASURED-BEST skeleton (R4: CPS=8, 1024 thr, PULL halos,
// HW cluster.sync = 619us; push and CPS=16 both falsified at ~850us).
// Change vs R4: own cur rows carried in REGISTERS across steps — removes the
// two redundant own-row SMEM reloads per thread per step (4->2 LDS float4,
// -33% crossbar traffic, two 29-cyc LDS chains off the critical path).

#define NT   500
#define NS   8
#define NZ   256
#define NX   256
#define NREC 128
#define CPS  8              // CTAs per shot == cluster size (portable)
#define ROWS 32             // NZ / CPS rows per CTA
#define TPB  1024
#define DT_OVER_DX 1.0e-4f  // 0.001 / 10.0

__global__ void __cluster_dims__(CPS, 1, 1) __launch_bounds__(TPB, 1)
wave_cluster_kernel(const float* __restrict__ x,    // (NT, NS)
                    const float* __restrict__ vp,   // (NZ, NX)
                    const int*   __restrict__ src,  // (NS, 2)
                    const int*   __restrict__ rec,  // (NS, NREC, 2)
                    float*       __restrict__ out)  // (NT, NS, NREC)
{
    extern __shared__ float smem[];
    float* bufA = smem;                 // ROWS*NX floats = 32 KB
    float* bufB = smem + ROWS * NX;     // 32 KB

    cg::cluster_group cluster = cg::this_cluster();
    const int rank = cluster.block_rank();        // 0..7 (z-slab index)
    const int shot = blockIdx.x / CPS;            // 0..7
    const int tid  = threadIdx.x;
    const int lane = tid & 31;
    const int x4   = tid & 63;                    // float4 column 0..63
    const int xs4  = x4 * 4;                      // scalar column of .x
    const int zg   = tid >> 6;                    // 0..15, two rows each (warp-uniform)
    const int zl0  = zg * 2;                      // local rows zl0, zl0+1
    const int gz0  = rank * ROWS + zl0;           // global z of row 0

    float4* Av = (float4*)bufA;
    float4* Bv = (float4*)bufB;
    const float4 zero4 = make_float4(0.f, 0.f, 0.f, 0.f);

    // ---- init: zero both buffers (step-0 neighbor reads see zeros) ----
    Av[zl0 * 64 + x4]       = zero4;
    Av[(zl0 + 1) * 64 + x4] = zero4;
    Bv[zl0 * 64 + x4]       = zero4;
    Bv[(zl0 + 1) * 64 + x4] = zero4;

    // ---- c2 = (vp * DT/DX)^2 into registers ----
    float4 c2a, c2b;
    {
        const float4* vpv = (const float4*)vp;
        float4 v0 = vpv[gz0 * 64 + x4];
        float4 v1 = vpv[(gz0 + 1) * 64 + x4];
        c2a.x = v0.x * DT_OVER_DX; c2a.y = v0.y * DT_OVER_DX;
        c2a.z = v0.z * DT_OVER_DX; c2a.w = v0.w * DT_OVER_DX;
        c2b.x = v1.x * DT_OVER_DX; c2b.y = v1.y * DT_OVER_DX;
        c2b.z = v1.z * DT_OVER_DX; c2b.w = v1.w * DT_OVER_DX;
        c2a.x *= c2a.x; c2a.y *= c2a.y; c2a.z *= c2a.z; c2a.w *= c2a.w;
        c2b.x *= c2b.x; c2b.y *= c2b.y; c2b.z *= c2b.z; c2b.w *= c2b.w;
    }

    // ---- source cell ownership ----
    const int sz  = src[2 * shot];
    const int sx  = src[2 * shot + 1];
    const int sx4 = sx >> 2;
    const int sxl = sx & 3;
    const bool src0 = (sz == gz0)     && (sx4 == x4);
    const bool src1 = (sz == gz0 + 1) && (sx4 == x4);
    const float* __restrict__ xs = x + shot;      // x[t*NS + shot] = xs[t*NS]

    // ---- receiver assignment: thread tid<128 owns receiver tid of this shot ----
    int  rzl = 0, rxp = 0;
    bool mine = false;
    if (tid < NREC) {
        int rz = rec[(shot * NREC + tid) * 2];
        rxp    = rec[(shot * NREC + tid) * 2 + 1];
        mine   = ((rz >> 5) == rank);             // ROWS == 32
        rzl    = rz & 31;
    }
    float* __restrict__ outp = out + shot * NREC + tid;   // += NS*NREC per step

    // ---- remote halo pointers for PULL (fixed for the whole run) ----
    float4* upA = (rank > 0)       ? (float4*)cluster.map_shared_rank((void*)bufA, rank - 1) : nullptr;
    float4* upB = (rank > 0)       ? (float4*)cluster.map_shared_rank((void*)bufB, rank - 1) : nullptr;
    float4* dnA = (rank < CPS - 1) ? (float4*)cluster.map_shared_rank((void*)bufA, rank + 1) : nullptr;
    float4* dnB = (rank < CPS - 1) ? (float4*)cluster.map_shared_rank((void*)bufB, rank + 1) : nullptr;

    float4 c0  = zero4, c1  = zero4;   // CUR p(t) own rows — register-carried
    float4 pva = zero4, pvb = zero4;   // prev p(t-1) own rows

    cluster.sync();   // zeros visible cluster-wide before step 0 halo reads

    #pragma unroll 1
    for (int t = 0; t < NT; ++t) {
        const bool odd = (t & 1) != 0;
        float4* curv   = odd ? Bv  : Av;   // holds p(t) (stored last step)
        float4* nxtv   = odd ? Av  : Bv;
        float4* upRem  = odd ? upB : upA;
        float4* dnRem  = odd ? dnB : dnA;
        float*  curs   = (float*)curv;

        // ---- neighbor rows only (own rows live in c0/c1 registers) ----
        float4 rm1, r2;
        if (zg > 0)  rm1 = curv[(zl0 - 1) * 64 + x4];
        else         rm1 = upRem ? upRem[(ROWS - 1) * 64 + x4] : zero4;
        if (zg < 15) r2  = curv[(zl0 + 2) * 64 + x4];
        else         r2  = dnRem ? dnRem[x4] : zero4;

        // x-neighbors from register cur via shfl; warp-edge via SMEM fallback
        float L0 = __shfl_up_sync(0xffffffffu, c0.w, 1);
        float R0 = __shfl_down_sync(0xffffffffu, c0.x, 1);
        float L1 = __shfl_up_sync(0xffffffffu, c1.w, 1);
        float R1 = __shfl_down_sync(0xffffffffu, c1.x, 1);
        if (lane == 0) {
            L0 = (x4 == 0) ? 0.f : curs[zl0 * NX + xs4 - 1];
            L1 = (x4 == 0) ? 0.f : curs[(zl0 + 1) * NX + xs4 - 1];
        }
        if (lane == 31) {
            R0 = (x4 == 63) ? 0.f : curs[zl0 * NX + xs4 + 4];
            R1 = (x4 == 63) ? 0.f : curs[(zl0 + 1) * NX + xs4 + 4];
        }

        // row zl0: up=rm1, dn=c1
        float4 lap0;
        lap0.x = rm1.x + c1.x + L0   + c0.y - 4.f * c0.x;
        lap0.y = rm1.y + c1.y + c0.x + c0.z - 4.f * c0.y;
        lap0.z = rm1.z + c1.z + c0.y + c0.w - 4.f * c0.z;
        lap0.w = rm1.w + c1.w + c0.z + R0   - 4.f * c0.w;
        float4 p0;
        p0.x = 2.f * c0.x - pva.x + c2a.x * lap0.x;
        p0.y = 2.f * c0.y - pva.y + c2a.y * lap0.y;
        p0.z = 2.f * c0.z - pva.z + c2a.z * lap0.z;
        p0.w = 2.f * c0.w - pva.w + c2a.w * lap0.w;

        // row zl0+1: up=c0, dn=r2
        float4 lap1;
        lap1.x = c0.x + r2.x + L1   + c1.y - 4.f * c1.x;
        lap1.y = c0.y + r2.y + c1.x + c1.z - 4.f * c1.y;
        lap1.z = c0.z + r2.z + c1.y + c1.w - 4.f * c1.z;
        lap1.w = c0.w + r2.w + c1.z + R1   - 4.f * c1.w;
        float4 p1;
        p1.x = 2.f * c1.x - pvb.x + c2b.x * lap1.x;
        p1.y = 2.f * c1.y - pvb.y + c2b.y * lap1.y;
        p1.z = 2.f * c1.z - pvb.z + c2b.z * lap1.z;
        p1.w = 2.f * c1.w - pvb.w + c2b.w * lap1.w;

        // source injection
        if (src0 | src1) {
            int t_off = (t + 2 < NT - 1) ? (t + 2) : (NT - 1);
            float amp = xs[t_off * NS] + xs[t * NS];
            if (src0) {
                if      (sxl == 0) p0.x += amp;
                else if (sxl == 1) p0.y += amp;
                else if (sxl == 2) p0.z += amp;
                else               p0.w += amp;
            } else {
                if      (sxl == 0) p1.x += amp;
                else if (sxl == 1) p1.y += amp;
                else if (sxl == 2) p1.z += amp;
                else               p1.w += amp;
            }
        }

        // register rotation: prev <- cur, cur <- next
        pva = c0; pvb = c1;
        c0  = p0; c1  = p1;

        // publish for neighbors (and receiver gather)
        nxtv[zl0 * 64 + x4]       = p0;
        nxtv[(zl0 + 1) * 64 + x4] = p1;

        cluster.sync();   // step t complete cluster-wide

        // receiver gather for step t (reads just-written buffer)
        if (mine) {
            const float* ns = (const float*)nxtv;
            outp[t * (NS * NREC)] = ns[rzl * NX + rxp];
        }
    }
}

extern "C" void kernel_launch(void* const* d_in, const int* in_sizes, int n_in,
                              void* d_out, int out_size)
{
    const float* x   = (const float*)d_in[0];
    const float* vp  = (const float*)d_in[1];
    const int*   src = (const int*)d_in[2];
    const int*   rec = (const int*)d_in[3];
    float*       out = (float*)d_out;
    (void)in_sizes; (void)n_in; (void)out_size;

    const size_t smem_bytes = 2u * ROWS * NX * sizeof(float);   // 64 KB
    cudaFuncSetAttribute(wave_cluster_kernel,
                         cudaFuncAttributeMaxDynamicSharedMemorySize,
                         (int)smem_bytes);

    wave_cluster_kernel<<<NS * CPS, TPB, smem_bytes>>>(x, vp, src, rec, out);
}